// round 2
// baseline (speedup 1.0000x reference)
#include <cuda_runtime.h>
#include <stdint.h>

#define NN 100000
#define FIN 128
#define HID 32
#define G3 96
#define NE 3200000

// ---- device scratch (static, allowed) ----
__device__ float g_dinv[NN];                  // deg -> rsqrt(deg), in place
__device__ float g_U[(size_t)NN * G3];        // x @ [Vc_z|Vc_r|Vc_h]
__device__ float g_agg[(size_t)NN * G3];      // A @ U
__device__ float g_Vc[FIN * G3];              // folded conv->linear weights
__device__ float g_cst[G3];                   // bc_g @ Wl_g1^T + bl_g
__device__ float g_Wt[3 * HID * HID];         // [g][k][j] = Wl_g[j][32+k]
__device__ int   g_is64;                      // 1 if edge_index is int64

// edge index loader: layout decided at runtime by detect_kernel
__device__ __forceinline__ int edge_idx(const void* ei, size_t pos) {
    if (g_is64) return (int)__ldg(((const long long*)ei) + pos);
    return __ldg(((const int*)ei) + pos);
}

// ---------------------------------------------------------------------------
// K-1: detect edge_index dtype. If int64 (values < 2^31), all odd 32-bit
// words are zero. If int32, odd words are random node ids (mostly nonzero).
// ---------------------------------------------------------------------------
__global__ void detect_kernel(const int* __restrict__ ei_words) {
    __shared__ int nz;
    if (threadIdx.x == 0) nz = 0;
    __syncthreads();
    // scan 4096 words = 2048 odd (hi) words
    for (int i = threadIdx.x; i < 4096; i += blockDim.x)
        if ((i & 1) && ei_words[i] != 0) atomicOr(&nz, 1);
    __syncthreads();
    if (threadIdx.x == 0) g_is64 = (nz == 0) ? 1 : 0;
}

// ---------------------------------------------------------------------------
// K0: fold weights.  Vc[k][g*32+j] = sum_t Wc_g[k][t] * Wl_g[j][t]
// ---------------------------------------------------------------------------
__global__ void prep_kernel(
    const float* Wc0, const float* bc0, const float* Wl0, const float* bl0,
    const float* Wc1, const float* bc1, const float* Wl1, const float* bl1,
    const float* Wc2, const float* bc2, const float* Wl2, const float* bl2)
{
    const float* Wc[3] = {Wc0, Wc1, Wc2};
    const float* bc[3] = {bc0, bc1, bc2};
    const float* Wl[3] = {Wl0, Wl1, Wl2};
    const float* bl[3] = {bl0, bl1, bl2};
    int t = threadIdx.x;            // 128 threads
    int k = t;                      // one x-feature row per thread
    for (int g = 0; g < 3; g++) {
        const float* wc_row = Wc[g] + (size_t)k * HID;
        for (int j = 0; j < HID; j++) {
            const float* wl_row = Wl[g] + (size_t)j * 2 * HID;
            float s = 0.f;
            #pragma unroll
            for (int tt = 0; tt < HID; tt++) s += wc_row[tt] * wl_row[tt];
            g_Vc[k * G3 + g * HID + j] = s;
        }
    }
    if (t < G3) {
        int g = t / HID, j = t % HID;
        const float* wl_row = Wl[g] + (size_t)j * 2 * HID;
        float s = bl[g][j];
        #pragma unroll
        for (int tt = 0; tt < HID; tt++) s += bc[g][tt] * wl_row[tt];
        g_cst[t] = s;
        for (int k2 = 0; k2 < HID; k2++)
            g_Wt[g * HID * HID + k2 * HID + j] = wl_row[HID + k2];
    }
}

// ---------------------------------------------------------------------------
// Degree (self-loop weight 1.0 baked into init), then rsqrt.
// ---------------------------------------------------------------------------
__global__ void deg_init_kernel() {
    int i = blockIdx.x * blockDim.x + threadIdx.x;
    if (i < NN) g_dinv[i] = 1.0f;
}

__global__ void deg_acc_kernel(const void* __restrict__ ei,
                               const float* __restrict__ ew) {
    int e = blockIdx.x * blockDim.x + threadIdx.x;
    if (e < NE) {
        int c = edge_idx(ei, (size_t)NE + e);   // col
        atomicAdd(&g_dinv[c], ew[e]);
    }
}

__global__ void deg_inv_kernel() {
    int i = blockIdx.x * blockDim.x + threadIdx.x;
    if (i < NN) g_dinv[i] = rsqrtf(g_dinv[i]);   // deg >= 1 always (self loop)
}

// ---------------------------------------------------------------------------
// K4: U = x @ Vc  (100000 x 128 @ 128 x 96), fused agg self-loop init.
// ---------------------------------------------------------------------------
__global__ void __launch_bounds__(256) gemm_u_kernel(const float* __restrict__ x) {
    __shared__ float xs[32][33];     // [node][k]
    __shared__ float vs[32][96];     // [k][j]
    int tid = threadIdx.x;
    int rg  = tid >> 5;              // 0..7  -> node group
    int cj  = tid & 31;              // 0..31 -> feature lane
    int m0  = blockIdx.x * 32;

    float acc[4][3] = {};
    for (int kb = 0; kb < FIN; kb += 32) {
        #pragma unroll
        for (int i = 0; i < 4; i++) {
            int idx = tid + i * 256;
            int m = idx >> 5, kk = idx & 31;
            xs[m][kk] = x[(size_t)(m0 + m) * FIN + kb + kk];
        }
        #pragma unroll
        for (int i = 0; i < 12; i++) {
            int idx = tid + i * 256;
            int kk = idx / 96, j = idx % 96;
            vs[kk][j] = g_Vc[(kb + kk) * G3 + j];
        }
        __syncthreads();
        #pragma unroll
        for (int kk = 0; kk < 32; kk++) {
            float b0 = vs[kk][cj], b1 = vs[kk][cj + 32], b2 = vs[kk][cj + 64];
            #pragma unroll
            for (int i = 0; i < 4; i++) {
                float a = xs[rg * 4 + i][kk];
                acc[i][0] += a * b0;
                acc[i][1] += a * b1;
                acc[i][2] += a * b2;
            }
        }
        __syncthreads();
    }
    #pragma unroll
    for (int i = 0; i < 4; i++) {
        int n = m0 + rg * 4 + i;
        float di = g_dinv[n];
        float sl = di * di;          // self-loop norm (w=1)
        #pragma unroll
        for (int t2 = 0; t2 < 3; t2++) {
            size_t off = (size_t)n * G3 + cj + t2 * 32;
            float v = acc[i][t2];
            g_U[off]   = v;
            g_agg[off] = v * sl;
        }
    }
}

// ---------------------------------------------------------------------------
// K5: edge scatter. One warp per edge; 3 atomics per lane (96 feats/edge).
// ---------------------------------------------------------------------------
__global__ void __launch_bounds__(256) edge_agg_kernel(const void* __restrict__ ei,
                                                       const float* __restrict__ ew) {
    int e = (int)((blockIdx.x * (unsigned)blockDim.x + threadIdx.x) >> 5);
    if (e >= NE) return;
    int lane = threadIdx.x & 31;

    int   r  = edge_idx(ei, e);
    int   c  = edge_idx(ei, (size_t)NE + e);
    float w  = __ldg(&ew[e]);
    float nw = g_dinv[r] * w * g_dinv[c];

    const float* u = g_U   + (size_t)r * G3;
    float*       a = g_agg + (size_t)c * G3;
    #pragma unroll
    for (int t2 = 0; t2 < 3; t2++) {
        int f = lane + t2 * 32;
        atomicAdd(a + f, nw * __ldg(u + f));
    }
}

// ---------------------------------------------------------------------------
// K6: per-node gates + head. One warp per node (lane = hidden feature j).
// ---------------------------------------------------------------------------
__global__ void __launch_bounds__(256) gates_kernel(const float* __restrict__ hprev,
                                                    const float* __restrict__ whead,
                                                    const float* __restrict__ bhead,
                                                    float* __restrict__ out) {
    __shared__ float Ws[3 * HID * HID];   // [g][k][j], lane-contiguous in j
    __shared__ float csts[G3];
    int tid = threadIdx.x;
    for (int i = tid; i < 3 * HID * HID; i += 256) Ws[i] = g_Wt[i];
    if (tid < G3) csts[tid] = g_cst[tid];
    __syncthreads();

    int warp = tid >> 5, lane = tid & 31;
    int n = blockIdx.x * 8 + warp;       // grid = 12500 -> exactly N nodes

    float h = hprev[(size_t)n * HID + lane];
    const float* ag = g_agg + (size_t)n * G3;
    float zp = ag[lane]      + csts[lane];
    float rp = ag[lane + 32] + csts[lane + 32];
    float hp = ag[lane + 64] + csts[lane + 64];

    const float* Wz = Ws;
    const float* Wr = Ws + HID * HID;
    const float* Wh = Ws + 2 * HID * HID;
    #pragma unroll
    for (int k = 0; k < HID; k++) {
        float hk = __shfl_sync(0xffffffffu, h, k);
        zp += hk * Wz[k * HID + lane];
        rp += hk * Wr[k * HID + lane];
    }
    float Z = 1.f / (1.f + __expf(-zp));
    float R = 1.f / (1.f + __expf(-rp));
    float hr = h * R;
    #pragma unroll
    for (int k = 0; k < HID; k++) {
        float hk = __shfl_sync(0xffffffffu, hr, k);
        hp += hk * Wh[k * HID + lane];
    }
    float Ht = tanhf(hp);
    float Hn = Z * h + (1.f - Z) * Ht;

    out[(size_t)NN + (size_t)n * HID + lane] = Hn;   // Hnew after y

    float yv = fmaxf(Hn, 0.f) * __ldg(&whead[lane]);
    #pragma unroll
    for (int off = 16; off > 0; off >>= 1)
        yv += __shfl_down_sync(0xffffffffu, yv, off);
    if (lane == 0) out[n] = yv + __ldg(bhead);
}

// ---------------------------------------------------------------------------
extern "C" void kernel_launch(void* const* d_in, const int* in_sizes, int n_in,
                              void* d_out, int out_size) {
    const float* x     = (const float*)d_in[0];
    const void*  ei    = d_in[1];
    const float* ew    = (const float*)d_in[2];
    const float* hprev = (const float*)d_in[3];
    const float* Wc[3], *bc[3], *Wl[3], *bl[3];
    for (int g = 0; g < 3; g++) {
        Wc[g] = (const float*)d_in[4 + g * 4];
        bc[g] = (const float*)d_in[5 + g * 4];
        Wl[g] = (const float*)d_in[6 + g * 4];
        bl[g] = (const float*)d_in[7 + g * 4];
    }
    const float* whead = (const float*)d_in[16];
    const float* bhead = (const float*)d_in[17];
    float* out = (float*)d_out;

    detect_kernel<<<1, 256>>>((const int*)ei);
    prep_kernel<<<1, 128>>>(Wc[0], bc[0], Wl[0], bl[0],
                            Wc[1], bc[1], Wl[1], bl[1],
                            Wc[2], bc[2], Wl[2], bl[2]);
    deg_init_kernel<<<(NN + 255) / 256, 256>>>();
    deg_acc_kernel<<<(NE + 255) / 256, 256>>>(ei, ew);
    deg_inv_kernel<<<(NN + 255) / 256, 256>>>();
    gemm_u_kernel<<<NN / 32, 256>>>(x);
    edge_agg_kernel<<<NE / 8, 256>>>(ei, ew);
    gates_kernel<<<NN / 8, 256>>>(hprev, whead, bhead, out);
}

// round 3
// speedup vs baseline: 1.3880x; 1.3880x over previous
#include <cuda_runtime.h>
#include <stdint.h>

#define NN 100000
#define FIN 128
#define HID 32
#define G3 96
#define NE 3200000

// ---- device scratch (static, allowed) ----
__device__ float g_dinv[NN];
__device__ float g_deg[NN];
__device__ int   g_cnt[NN];
__device__ int   g_rowstart[NN];
__device__ int   g_cursor[NN];
__device__ int   g_bsum[128];                  // block partial sums for scan
__device__ unsigned long long g_edges[NE];     // packed (row:int32, norm_w:f32)
__device__ float g_U[(size_t)NN * G3];         // x @ [Vc_z|Vc_r|Vc_h]
__device__ float g_Vc[FIN * G3];               // folded conv->linear weights
__device__ float g_cst[G3];                    // bc_g @ Wl_g1^T + bl_g
__device__ float g_Wt[3 * HID * HID];          // [g][k][j] = Wl_g[j][32+k]
__device__ int   g_is64;

__device__ __forceinline__ int edge_idx(const void* ei, size_t pos) {
    if (g_is64) return (int)__ldg(((const long long*)ei) + pos);
    return __ldg(((const int*)ei) + pos);
}

// ---------------------------------------------------------------------------
// detect edge_index dtype (int64 -> all hi words zero)
// ---------------------------------------------------------------------------
__global__ void detect_kernel(const int* __restrict__ ei_words) {
    __shared__ int nz;
    if (threadIdx.x == 0) nz = 0;
    __syncthreads();
    for (int i = threadIdx.x; i < 4096; i += blockDim.x)
        if ((i & 1) && ei_words[i] != 0) atomicOr(&nz, 1);
    __syncthreads();
    if (threadIdx.x == 0) g_is64 = (nz == 0) ? 1 : 0;
}

// ---------------------------------------------------------------------------
// fold weights
// ---------------------------------------------------------------------------
__global__ void prep_kernel(
    const float* Wc0, const float* bc0, const float* Wl0, const float* bl0,
    const float* Wc1, const float* bc1, const float* Wl1, const float* bl1,
    const float* Wc2, const float* bc2, const float* Wl2, const float* bl2)
{
    const float* Wc[3] = {Wc0, Wc1, Wc2};
    const float* bc[3] = {bc0, bc1, bc2};
    const float* Wl[3] = {Wl0, Wl1, Wl2};
    const float* bl[3] = {bl0, bl1, bl2};
    int t = threadIdx.x;            // 128 threads
    int k = t;
    for (int g = 0; g < 3; g++) {
        const float* wc_row = Wc[g] + (size_t)k * HID;
        for (int j = 0; j < HID; j++) {
            const float* wl_row = Wl[g] + (size_t)j * 2 * HID;
            float s = 0.f;
            #pragma unroll
            for (int tt = 0; tt < HID; tt++) s += wc_row[tt] * wl_row[tt];
            g_Vc[k * G3 + g * HID + j] = s;
        }
    }
    if (t < G3) {
        int g = t / HID, j = t % HID;
        const float* wl_row = Wl[g] + (size_t)j * 2 * HID;
        float s = bl[g][j];
        #pragma unroll
        for (int tt = 0; tt < HID; tt++) s += bc[g][tt] * wl_row[tt];
        g_cst[t] = s;
        for (int k2 = 0; k2 < HID; k2++)
            g_Wt[g * HID * HID + k2 * HID + j] = wl_row[HID + k2];
    }
}

// ---------------------------------------------------------------------------
// init deg (self-loop w=1) and counts
// ---------------------------------------------------------------------------
__global__ void init_kernel() {
    int i = blockIdx.x * blockDim.x + threadIdx.x;
    if (i < NN) { g_deg[i] = 1.0f; g_cnt[i] = 0; }
}

// ---------------------------------------------------------------------------
// count in-edges per col + accumulate weighted degree
// ---------------------------------------------------------------------------
__global__ void count_kernel(const void* __restrict__ ei,
                             const float* __restrict__ ew) {
    int e = blockIdx.x * blockDim.x + threadIdx.x;
    if (e < NE) {
        int c = edge_idx(ei, (size_t)NE + e);
        atomicAdd(&g_cnt[c], 1);
        atomicAdd(&g_deg[c], __ldg(&ew[e]));
    }
}

// ---------------------------------------------------------------------------
// 3-kernel exclusive scan of g_cnt -> g_rowstart (+cursor copy, +dinv)
// ---------------------------------------------------------------------------
__global__ void __launch_bounds__(1024) scanA_kernel() {
    __shared__ int wsum[32];
    int tid = threadIdx.x, lane = tid & 31, wid = tid >> 5;
    int i = blockIdx.x * 1024 + tid;
    int v = (i < NN) ? g_cnt[i] : 0;
    int s = v;
    #pragma unroll
    for (int off = 1; off < 32; off <<= 1) {
        int t = __shfl_up_sync(0xffffffffu, s, off);
        if (lane >= off) s += t;
    }
    if (lane == 31) wsum[wid] = s;
    __syncthreads();
    if (wid == 0) {
        int t = wsum[lane];
        #pragma unroll
        for (int off = 1; off < 32; off <<= 1) {
            int u = __shfl_up_sync(0xffffffffu, t, off);
            if (lane >= off) t += u;
        }
        wsum[lane] = t;
    }
    __syncthreads();
    int woff = (wid > 0) ? wsum[wid - 1] : 0;
    if (i < NN) g_rowstart[i] = s - v + woff;      // exclusive within block
    if (tid == 1023) g_bsum[blockIdx.x] = s + woff;
}

__global__ void scanB_kernel(int nblk) {    // 1 block, 128 threads
    __shared__ int tmp[128];
    int t = threadIdx.x;
    tmp[t] = (t < nblk) ? g_bsum[t] : 0;
    __syncthreads();
    if (t == 0) {
        int acc = 0;
        for (int i = 0; i < nblk; i++) { int v = tmp[i]; tmp[i] = acc; acc += v; }
    }
    __syncthreads();
    if (t < nblk) g_bsum[t] = tmp[t];
}

__global__ void __launch_bounds__(1024) scanC_kernel() {
    int i = blockIdx.x * 1024 + threadIdx.x;
    if (i < NN) {
        int rs = g_rowstart[i] + g_bsum[blockIdx.x];
        g_rowstart[i] = rs;
        g_cursor[i]   = rs;
        g_dinv[i]     = rsqrtf(g_deg[i]);
    }
}

// ---------------------------------------------------------------------------
// scatter edges into CSR buckets with precomputed normalized weight
// ---------------------------------------------------------------------------
__global__ void scatter_kernel(const void* __restrict__ ei,
                               const float* __restrict__ ew) {
    int e = blockIdx.x * blockDim.x + threadIdx.x;
    if (e >= NE) return;
    int   r  = edge_idx(ei, e);
    int   c  = edge_idx(ei, (size_t)NE + e);
    float nw = g_dinv[r] * __ldg(&ew[e]) * g_dinv[c];
    int pos = atomicAdd(&g_cursor[c], 1);
    g_edges[pos] = (unsigned long long)(unsigned)r |
                   ((unsigned long long)__float_as_uint(nw) << 32);
}

// ---------------------------------------------------------------------------
// U = x @ Vc  (100000 x 128 @ 128 x 96)
// ---------------------------------------------------------------------------
__global__ void __launch_bounds__(256) gemm_u_kernel(const float* __restrict__ x) {
    __shared__ float xs[32][33];
    __shared__ float vs[32][96];
    int tid = threadIdx.x;
    int rg  = tid >> 5;
    int cj  = tid & 31;
    int m0  = blockIdx.x * 32;

    float acc[4][3] = {};
    for (int kb = 0; kb < FIN; kb += 32) {
        #pragma unroll
        for (int i = 0; i < 4; i++) {
            int idx = tid + i * 256;
            int m = idx >> 5, kk = idx & 31;
            xs[m][kk] = x[(size_t)(m0 + m) * FIN + kb + kk];
        }
        #pragma unroll
        for (int i = 0; i < 12; i++) {
            int idx = tid + i * 256;
            int kk = idx / 96, j = idx % 96;
            vs[kk][j] = g_Vc[(kb + kk) * G3 + j];
        }
        __syncthreads();
        #pragma unroll
        for (int kk = 0; kk < 32; kk++) {
            float b0 = vs[kk][cj], b1 = vs[kk][cj + 32], b2 = vs[kk][cj + 64];
            #pragma unroll
            for (int i = 0; i < 4; i++) {
                float a = xs[rg * 4 + i][kk];
                acc[i][0] += a * b0;
                acc[i][1] += a * b1;
                acc[i][2] += a * b2;
            }
        }
        __syncthreads();
    }
    #pragma unroll
    for (int i = 0; i < 4; i++) {
        int n = m0 + rg * 4 + i;
        #pragma unroll
        for (int t2 = 0; t2 < 3; t2++)
            g_U[(size_t)n * G3 + cj + t2 * 32] = acc[i][t2];
    }
}

// ---------------------------------------------------------------------------
// fused gather + gates + head. Warp per node, lane = hidden feature.
// ---------------------------------------------------------------------------
__global__ void __launch_bounds__(256) gather_gates_kernel(
    const float* __restrict__ hprev,
    const float* __restrict__ whead,
    const float* __restrict__ bhead,
    float* __restrict__ out)
{
    __shared__ float Ws[3 * HID * HID];
    __shared__ float csts[G3];
    int tid = threadIdx.x;
    for (int i = tid; i < 3 * HID * HID; i += 256) Ws[i] = g_Wt[i];
    if (tid < G3) csts[tid] = g_cst[tid];
    __syncthreads();

    int warp = tid >> 5, lane = tid & 31;
    int n = blockIdx.x * 8 + warp;       // grid = 12500 -> exactly N nodes

    // self-loop init
    float di = g_dinv[n];
    float sl = di * di;
    const float* un = g_U + (size_t)n * G3;
    float a0 = un[lane]      * sl;
    float a1 = un[lane + 32] * sl;
    float a2 = un[lane + 64] * sl;

    // gather in-edges
    int start = g_rowstart[n];
    int cnt   = g_cnt[n];
    for (int b = 0; b < cnt; b += 32) {
        int m = min(32, cnt - b);
        unsigned long long pk = 0;
        if (lane < m) pk = __ldg(&g_edges[start + b + lane]);
        for (int j = 0; j < m; j++) {
            unsigned long long p = __shfl_sync(0xffffffffu, pk, j);
            int   r  = (int)(unsigned)(p & 0xffffffffu);
            float nw = __uint_as_float((unsigned)(p >> 32));
            const float* ur = g_U + (size_t)r * G3;
            a0 += nw * __ldg(ur + lane);
            a1 += nw * __ldg(ur + lane + 32);
            a2 += nw * __ldg(ur + lane + 64);
        }
    }

    // gates
    float h  = hprev[(size_t)n * HID + lane];
    float zp = a0 + csts[lane];
    float rp = a1 + csts[lane + 32];
    float hp = a2 + csts[lane + 64];

    const float* Wz = Ws;
    const float* Wr = Ws + HID * HID;
    const float* Wh = Ws + 2 * HID * HID;
    #pragma unroll
    for (int k = 0; k < HID; k++) {
        float hk = __shfl_sync(0xffffffffu, h, k);
        zp += hk * Wz[k * HID + lane];
        rp += hk * Wr[k * HID + lane];
    }
    float Z = 1.f / (1.f + __expf(-zp));
    float R = 1.f / (1.f + __expf(-rp));
    float hr = h * R;
    #pragma unroll
    for (int k = 0; k < HID; k++) {
        float hk = __shfl_sync(0xffffffffu, hr, k);
        hp += hk * Wh[k * HID + lane];
    }
    float Ht = tanhf(hp);
    float Hn = Z * h + (1.f - Z) * Ht;

    out[(size_t)NN + (size_t)n * HID + lane] = Hn;

    float yv = fmaxf(Hn, 0.f) * __ldg(&whead[lane]);
    #pragma unroll
    for (int off = 16; off > 0; off >>= 1)
        yv += __shfl_down_sync(0xffffffffu, yv, off);
    if (lane == 0) out[n] = yv + __ldg(bhead);
}

// ---------------------------------------------------------------------------
extern "C" void kernel_launch(void* const* d_in, const int* in_sizes, int n_in,
                              void* d_out, int out_size) {
    const float* x     = (const float*)d_in[0];
    const void*  ei    = d_in[1];
    const float* ew    = (const float*)d_in[2];
    const float* hprev = (const float*)d_in[3];
    const float* Wc[3], *bc[3], *Wl[3], *bl[3];
    for (int g = 0; g < 3; g++) {
        Wc[g] = (const float*)d_in[4 + g * 4];
        bc[g] = (const float*)d_in[5 + g * 4];
        Wl[g] = (const float*)d_in[6 + g * 4];
        bl[g] = (const float*)d_in[7 + g * 4];
    }
    const float* whead = (const float*)d_in[16];
    const float* bhead = (const float*)d_in[17];
    float* out = (float*)d_out;

    const int nscan = (NN + 1023) / 1024;   // 98

    detect_kernel<<<1, 256>>>((const int*)ei);
    prep_kernel<<<1, 128>>>(Wc[0], bc[0], Wl[0], bl[0],
                            Wc[1], bc[1], Wl[1], bl[1],
                            Wc[2], bc[2], Wl[2], bl[2]);
    init_kernel<<<(NN + 255) / 256, 256>>>();
    count_kernel<<<(NE + 255) / 256, 256>>>(ei, ew);
    scanA_kernel<<<nscan, 1024>>>();
    scanB_kernel<<<1, 128>>>(nscan);
    scanC_kernel<<<nscan, 1024>>>();
    scatter_kernel<<<(NE + 255) / 256, 256>>>(ei, ew);
    gemm_u_kernel<<<NN / 32, 256>>>(x);
    gather_gates_kernel<<<NN / 8, 256>>>(hprev, whead, bhead, out);
}